// round 5
// baseline (speedup 1.0000x reference)
#include <cuda_runtime.h>
#include <math.h>
#include <stdint.h>

// ---------------- problem constants ----------------
#define T_TOK 4096
#define H_DIM 2048
#define E_EXP 32
#define NE    48
#define I_DIM 1024
#define TOPK  6
#define ROUTED_SCALE 2.5f
#define CAP   4096

// ---------------- device scratch (static, no allocs) ----------------
__device__ int   g_count[E_EXP];
__device__ int   g_tok[E_EXP * CAP];
__device__ int   g_nk[T_TOK];
__device__ int   g_slots[T_TOK * TOPK];
__device__ float g_wts[T_TOK * TOPK];
__device__ float g_zero_w[T_TOK];
__device__ float g_act[(size_t)E_EXP * CAP * I_DIM];
__device__ float g_y[(size_t)E_EXP * CAP * H_DIM];

// ---------------- kernel 0 ----------------
__global__ void zero_counts_kernel() {
    int i = threadIdx.x;
    if (i < E_EXP) g_count[i] = 0;
}

// ---------------- kernel 1: router (exact fp32 — selection must not flip) ----------------
__global__ __launch_bounds__(256)
void router_kernel(const float* __restrict__ x,
                   const float* __restrict__ rw,
                   const float* __restrict__ bias) {
    int t   = blockIdx.x;
    int tid = threadIdx.x;
    __shared__ float sx[H_DIM];
    __shared__ float slog[NE];

    const float* xrow = x + (size_t)t * H_DIM;
    for (int i = tid; i < H_DIM; i += 256) sx[i] = xrow[i];
    __syncthreads();

    int warp = tid >> 5, lane = tid & 31;
    for (int e = warp; e < NE; e += 8) {
        const float* w = rw + (size_t)e * H_DIM;
        float acc = 0.f;
        for (int i = lane; i < H_DIM; i += 32) acc += sx[i] * w[i];
        #pragma unroll
        for (int o = 16; o; o >>= 1) acc += __shfl_xor_sync(0xffffffffu, acc, o);
        if (lane == 0) slog[e] = acc;
    }
    __syncthreads();

    if (tid == 0) {
        float sc[NE], scc[NE];
        #pragma unroll
        for (int e = 0; e < NE; e++) {
            float s = 1.f / (1.f + expf(-slog[e]));
            sc[e]  = s;
            scc[e] = s + bias[e];
        }
        int ids[TOPK]; float wts[TOPK]; float sum = 0.f;
        bool used[NE];
        #pragma unroll
        for (int e = 0; e < NE; e++) used[e] = false;
        #pragma unroll
        for (int k = 0; k < TOPK; k++) {
            int bi = 0; float bv = -1e30f;
            for (int e = 0; e < NE; e++)
                if (!used[e] && scc[e] > bv) { bv = scc[e]; bi = e; }   // strict > : lowest idx on tie
            used[bi] = true; ids[k] = bi; wts[k] = sc[bi]; sum += sc[bi];
        }
        float inv = ROUTED_SCALE / sum;
        float zw = 0.f;
        int nk = 0;
        #pragma unroll
        for (int k = 0; k < TOPK; k++) {
            float w = wts[k] * inv;
            if (ids[k] >= E_EXP) {
                zw += w;
            } else {
                int e = ids[k];
                int pos = atomicAdd(&g_count[e], 1);
                g_tok[e * CAP + pos] = t;
                g_slots[t * TOPK + nk] = e * CAP + pos;
                g_wts[t * TOPK + nk] = w;
                nk++;
            }
        }
        g_nk[t] = nk;
        g_zero_w[t] = zw;
    }
}

// ---------------- tf32 mma helpers (legacy mma.sync — sm_103 base target OK) ----------------
__device__ __forceinline__ uint32_t f2tf(float f) {
    uint32_t r;
    asm("cvt.rna.tf32.f32 %0, %1;" : "=r"(r) : "f"(f));
    return r;
}
__device__ __forceinline__ void mma_tf32(float* d, const uint32_t* a, const uint32_t* b) {
    asm volatile(
        "mma.sync.aligned.m16n8k8.row.col.f32.tf32.tf32.f32 "
        "{%0,%1,%2,%3}, {%4,%5,%6,%7}, {%8,%9}, {%0,%1,%2,%3};\n"
        : "+f"(d[0]), "+f"(d[1]), "+f"(d[2]), "+f"(d[3])
        : "r"(a[0]), "r"(a[1]), "r"(a[2]), "r"(a[3]),
          "r"(b[0]), "r"(b[1]));
}
__device__ __forceinline__ uint4 cvt4(float4 v) {
    uint4 r;
    r.x = f2tf(v.x); r.y = f2tf(v.y); r.z = f2tf(v.z); r.w = f2tf(v.w);
    return r;
}

// ---------------- GEMM tiling ----------------
#define BM 128
#define BN 256
#define BK 16
#define SPAD 20                    // stride%32=20 -> conflict-free 8x4 fragment reads
#define ABUF (BM * SPAD)           // words
#define BBUF (BN * SPAD)
#define BUFW (ABUF + BBUF)         // words per buffer
#define SMEM_BYTES (2 * BUFW * 4)  // 61440 B

// kernel 2: act = silu(x@w1^T)*(x@w3^T); B rows interleaved w1/w3
__global__ __launch_bounds__(256, 1)
void gemm1_kernel(const float* __restrict__ x,
                  const float* __restrict__ w1,
                  const float* __restrict__ w3) {
    int e   = blockIdx.z;
    int cnt = g_count[e];
    int m0  = blockIdx.y * BM;
    if (m0 >= cnt) return;
    int f0  = blockIdx.x * (BN / 2);      // 128 features per block

    extern __shared__ uint32_t smw[];
    int tid = threadIdx.x, warp = tid >> 5, lane = tid & 31;
    int wm = warp >> 2, wn = warp & 3;    // 2x4 warp grid, warp tile 64x64
    int g = lane >> 2, tg = lane & 3;

    // staging assignment
    int ar = tid >> 1, ac = (tid & 1) * 8;
    int arow = m0 + ar; if (arow >= cnt) arow = cnt - 1;   // clamp; stores guarded
    int tok = g_tok[e * CAP + arow];
    const float* aptr = x + (size_t)tok * H_DIM;
    const float* bptr = ((tid & 1) ? w3 : w1)
                      + ((size_t)e * I_DIM + f0 + (tid >> 1)) * H_DIM;
    uint32_t aoff = ar * SPAD + ac;
    uint32_t boff = ABUF + tid * SPAD;

    float4 ra[2], rb[4];
    float acc[4][8][4];
    #pragma unroll
    for (int mt = 0; mt < 4; mt++)
        #pragma unroll
        for (int nt = 0; nt < 8; nt++)
            #pragma unroll
            for (int i = 0; i < 4; i++) acc[mt][nt][i] = 0.f;

    const int NKT = H_DIM / BK;  // 128

    // prologue
    ra[0] = *(const float4*)(aptr + ac);
    ra[1] = *(const float4*)(aptr + ac + 4);
    #pragma unroll
    for (int i = 0; i < 4; i++) rb[i] = *(const float4*)(bptr + 4 * i);
    {
        uint32_t* base = smw;
        *(uint4*)&base[aoff]     = cvt4(ra[0]);
        *(uint4*)&base[aoff + 4] = cvt4(ra[1]);
        #pragma unroll
        for (int i = 0; i < 4; i++) *(uint4*)&base[boff + 4 * i] = cvt4(rb[i]);
    }
    ra[0] = *(const float4*)(aptr + BK + ac);
    ra[1] = *(const float4*)(aptr + BK + ac + 4);
    #pragma unroll
    for (int i = 0; i < 4; i++) rb[i] = *(const float4*)(bptr + BK + 4 * i);
    __syncthreads();

    #pragma unroll 1
    for (int c = 0; c < NKT; c++) {
        int b = c & 1;
        if (c + 1 < NKT) {
            uint32_t* base = smw + (b ^ 1) * BUFW;
            *(uint4*)&base[aoff]     = cvt4(ra[0]);
            *(uint4*)&base[aoff + 4] = cvt4(ra[1]);
            #pragma unroll
            for (int i = 0; i < 4; i++) *(uint4*)&base[boff + 4 * i] = cvt4(rb[i]);
        }
        if (c + 2 < NKT) {
            int k0 = (c + 2) * BK;
            ra[0] = *(const float4*)(aptr + k0 + ac);
            ra[1] = *(const float4*)(aptr + k0 + ac + 4);
            #pragma unroll
            for (int i = 0; i < 4; i++) rb[i] = *(const float4*)(bptr + k0 + 4 * i);
        }
        {
            uint32_t* A = smw + b * BUFW;
            uint32_t* B = A + ABUF;
            #pragma unroll
            for (int k8 = 0; k8 < BK; k8 += 8) {
                uint32_t afr[4][4], bfr[8][2];
                #pragma unroll
                for (int mt = 0; mt < 4; mt++) {
                    int r0 = wm * 64 + mt * 16;
                    afr[mt][0] = A[(r0 + g)     * SPAD + k8 + tg];
                    afr[mt][1] = A[(r0 + g + 8) * SPAD + k8 + tg];
                    afr[mt][2] = A[(r0 + g)     * SPAD + k8 + tg + 4];
                    afr[mt][3] = A[(r0 + g + 8) * SPAD + k8 + tg + 4];
                }
                #pragma unroll
                for (int nt = 0; nt < 8; nt++) {
                    int c0 = wn * 64 + nt * 8 + g;
                    bfr[nt][0] = B[c0 * SPAD + k8 + tg];
                    bfr[nt][1] = B[c0 * SPAD + k8 + tg + 4];
                }
                #pragma unroll
                for (int mt = 0; mt < 4; mt++)
                    #pragma unroll
                    for (int nt = 0; nt < 8; nt++)
                        mma_tf32(acc[mt][nt], afr[mt], bfr[nt]);
            }
        }
        __syncthreads();
    }

    // epilogue: col 2j=gate, 2j+1=up -> silu(gate)*up
    #pragma unroll
    for (int mt = 0; mt < 4; mt++) {
        int row = m0 + wm * 64 + mt * 16 + g;
        #pragma unroll
        for (int nt = 0; nt < 8; nt++) {
            int f = f0 + wn * 32 + nt * 4 + tg;
            float* d = acc[mt][nt];
            if (row < cnt) {
                float gt = d[0], up = d[1];
                g_act[((size_t)e * CAP + row) * I_DIM + f] = gt / (1.f + expf(-gt)) * up;
            }
            if (row + 8 < cnt) {
                float gt = d[2], up = d[3];
                g_act[((size_t)e * CAP + row + 8) * I_DIM + f] = gt / (1.f + expf(-gt)) * up;
            }
        }
    }
}

// kernel 3: y = act @ w2^T (per-slot output, deterministic)
__global__ __launch_bounds__(256, 1)
void gemm2_kernel(const float* __restrict__ w2) {
    int e   = blockIdx.z;
    int cnt = g_count[e];
    int m0  = blockIdx.y * BM;
    if (m0 >= cnt) return;
    int n0  = blockIdx.x * BN;

    extern __shared__ uint32_t smw[];
    int tid = threadIdx.x, warp = tid >> 5, lane = tid & 31;
    int wm = warp >> 2, wn = warp & 3;
    int g = lane >> 2, tg = lane & 3;

    int ar = tid >> 1, ac = (tid & 1) * 8;
    int arow = m0 + ar; if (arow >= cnt) arow = cnt - 1;
    const float* aptr = g_act + ((size_t)e * CAP + arow) * I_DIM;
    const float* bptr = w2 + ((size_t)e * H_DIM + n0 + tid) * I_DIM;
    uint32_t aoff = ar * SPAD + ac;
    uint32_t boff = ABUF + tid * SPAD;

    float4 ra[2], rb[4];
    float acc[4][8][4];
    #pragma unroll
    for (int mt = 0; mt < 4; mt++)
        #pragma unroll
        for (int nt = 0; nt < 8; nt++)
            #pragma unroll
            for (int i = 0; i < 4; i++) acc[mt][nt][i] = 0.f;

    const int NKT = I_DIM / BK;  // 64

    ra[0] = *(const float4*)(aptr + ac);
    ra[1] = *(const float4*)(aptr + ac + 4);
    #pragma unroll
    for (int i = 0; i < 4; i++) rb[i] = *(const float4*)(bptr + 4 * i);
    {
        uint32_t* base = smw;
        *(uint4*)&base[aoff]     = cvt4(ra[0]);
        *(uint4*)&base[aoff + 4] = cvt4(ra[1]);
        #pragma unroll
        for (int i = 0; i < 4; i++) *(uint4*)&base[boff + 4 * i] = cvt4(rb[i]);
    }
    ra[0] = *(const float4*)(aptr + BK + ac);
    ra[1] = *(const float4*)(aptr + BK + ac + 4);
    #pragma unroll
    for (int i = 0; i < 4; i++) rb[i] = *(const float4*)(bptr + BK + 4 * i);
    __syncthreads();

    #pragma unroll 1
    for (int c = 0; c < NKT; c++) {
        int b = c & 1;
        if (c + 1 < NKT) {
            uint32_t* base = smw + (b ^ 1) * BUFW;
            *(uint4*)&base[aoff]     = cvt4(ra[0]);
            *(uint4*)&base[aoff + 4] = cvt4(ra[1]);
            #pragma unroll
            for (int i = 0; i < 4; i++) *(uint4*)&base[boff + 4 * i] = cvt4(rb[i]);
        }
        if (c + 2 < NKT) {
            int k0 = (c + 2) * BK;
            ra[0] = *(const float4*)(aptr + k0 + ac);
            ra[1] = *(const float4*)(aptr + k0 + ac + 4);
            #pragma unroll
            for (int i = 0; i < 4; i++) rb[i] = *(const float4*)(bptr + k0 + 4 * i);
        }
        {
            uint32_t* A = smw + b * BUFW;
            uint32_t* B = A + ABUF;
            #pragma unroll
            for (int k8 = 0; k8 < BK; k8 += 8) {
                uint32_t afr[4][4], bfr[8][2];
                #pragma unroll
                for (int mt = 0; mt < 4; mt++) {
                    int r0 = wm * 64 + mt * 16;
                    afr[mt][0] = A[(r0 + g)     * SPAD + k8 + tg];
                    afr[mt][1] = A[(r0 + g + 8) * SPAD + k8 + tg];
                    afr[mt][2] = A[(r0 + g)     * SPAD + k8 + tg + 4];
                    afr[mt][3] = A[(r0 + g + 8) * SPAD + k8 + tg + 4];
                }
                #pragma unroll
                for (int nt = 0; nt < 8; nt++) {
                    int c0 = wn * 64 + nt * 8 + g;
                    bfr[nt][0] = B[c0 * SPAD + k8 + tg];
                    bfr[nt][1] = B[c0 * SPAD + k8 + tg + 4];
                }
                #pragma unroll
                for (int mt = 0; mt < 4; mt++)
                    #pragma unroll
                    for (int nt = 0; nt < 8; nt++)
                        mma_tf32(acc[mt][nt], afr[mt], bfr[nt]);
            }
        }
        __syncthreads();
    }

    #pragma unroll
    for (int mt = 0; mt < 4; mt++) {
        int row = m0 + wm * 64 + mt * 16 + g;
        #pragma unroll
        for (int nt = 0; nt < 8; nt++) {
            int col = n0 + wn * 64 + nt * 8 + 2 * tg;
            float* d = acc[mt][nt];
            if (row < cnt)
                *(float2*)&g_y[((size_t)e * CAP + row) * H_DIM + col]
                    = make_float2(d[0], d[1]);
            if (row + 8 < cnt)
                *(float2*)&g_y[((size_t)e * CAP + row + 8) * H_DIM + col]
                    = make_float2(d[2], d[3]);
        }
    }
}

// ---------------- kernel 4: combine ----------------
__global__ __launch_bounds__(256)
void combine_kernel(const float* __restrict__ x, float* __restrict__ out) {
    int t = blockIdx.x;
    __shared__ int   s_n;
    __shared__ float s_zw;
    __shared__ int   s_slot[TOPK];
    __shared__ float s_w[TOPK];
    int tid = threadIdx.x;
    if (tid == 0) { s_n = g_nk[t]; s_zw = g_zero_w[t]; }
    if (tid < TOPK) { s_slot[tid] = g_slots[t * TOPK + tid]; s_w[tid] = g_wts[t * TOPK + tid]; }
    __syncthreads();
    int n = s_n; float zw = s_zw;

    const float* xrow = x + (size_t)t * H_DIM;
    float* orow = out + (size_t)t * H_DIM;
    for (int h = tid * 4; h < H_DIM; h += 256 * 4) {
        float4 xv = *(const float4*)(xrow + h);
        float4 o = make_float4(xv.x * zw, xv.y * zw, xv.z * zw, xv.w * zw);
        for (int k = 0; k < n; k++) {
            const float4 yv = *(const float4*)(g_y + (size_t)s_slot[k] * H_DIM + h);
            float wk = s_w[k];
            o.x += wk * yv.x; o.y += wk * yv.y; o.z += wk * yv.z; o.w += wk * yv.w;
        }
        *(float4*)(orow + h) = o;
    }
}

// ---------------- launcher ----------------
extern "C" void kernel_launch(void* const* d_in, const int* in_sizes, int n_in,
                              void* d_out, int out_size) {
    const float* x    = (const float*)d_in[0];
    const float* rw   = (const float*)d_in[1];
    const float* bias = (const float*)d_in[2];
    const float* w1   = (const float*)d_in[3];
    const float* w3   = (const float*)d_in[4];
    const float* w2   = (const float*)d_in[5];
    float* out = (float*)d_out;

    cudaFuncSetAttribute(gemm1_kernel, cudaFuncAttributeMaxDynamicSharedMemorySize, SMEM_BYTES);
    cudaFuncSetAttribute(gemm2_kernel, cudaFuncAttributeMaxDynamicSharedMemorySize, SMEM_BYTES);

    zero_counts_kernel<<<1, 32>>>();
    router_kernel<<<T_TOK, 256>>>(x, rw, bias);
    {
        dim3 g((2 * I_DIM) / BN, T_TOK / BM, E_EXP);  // 8 x 32 x 32
        gemm1_kernel<<<g, 256, SMEM_BYTES>>>(x, w1, w3);
    }
    {
        dim3 g(H_DIM / BN, T_TOK / BM, E_EXP);        // 8 x 32 x 32
        gemm2_kernel<<<g, 256, SMEM_BYTES>>>(w2);
    }
    combine_kernel<<<T_TOK, 256>>>(x, out);
}

// round 7
// speedup vs baseline: 1.0634x; 1.0634x over previous
#include <cuda_runtime.h>
#include <math.h>
#include <stdint.h>

// ---------------- problem constants ----------------
#define T_TOK 4096
#define H_DIM 2048
#define E_EXP 32
#define NE    48
#define I_DIM 1024
#define TOPK  6
#define ROUTED_SCALE 2.5f
#define CAP   4096

// ---------------- device scratch (static, no allocs) ----------------
__device__ int   g_count[E_EXP];
__device__ int   g_tok[E_EXP * CAP];
__device__ int   g_nk[T_TOK];
__device__ int   g_slots[T_TOK * TOPK];
__device__ float g_wts[T_TOK * TOPK];
__device__ float g_zero_w[T_TOK];
__device__ float g_act[(size_t)E_EXP * CAP * I_DIM];
__device__ float g_y[(size_t)E_EXP * CAP * H_DIM];

// ---------------- kernel 0 ----------------
__global__ void zero_counts_kernel() {
    int i = threadIdx.x;
    if (i < E_EXP) g_count[i] = 0;
}

// ---------------- kernel 1: router (exact fp32 — selection must not flip) ----------------
__global__ __launch_bounds__(256)
void router_kernel(const float* __restrict__ x,
                   const float* __restrict__ rw,
                   const float* __restrict__ bias) {
    int t   = blockIdx.x;
    int tid = threadIdx.x;
    __shared__ float sx[H_DIM];
    __shared__ float slog[NE];

    const float* xrow = x + (size_t)t * H_DIM;
    for (int i = tid; i < H_DIM; i += 256) sx[i] = xrow[i];
    __syncthreads();

    int warp = tid >> 5, lane = tid & 31;
    for (int e = warp; e < NE; e += 8) {
        const float* w = rw + (size_t)e * H_DIM;
        float acc = 0.f;
        for (int i = lane; i < H_DIM; i += 32) acc += sx[i] * w[i];
        #pragma unroll
        for (int o = 16; o; o >>= 1) acc += __shfl_xor_sync(0xffffffffu, acc, o);
        if (lane == 0) slog[e] = acc;
    }
    __syncthreads();

    if (tid == 0) {
        float sc[NE], scc[NE];
        #pragma unroll
        for (int e = 0; e < NE; e++) {
            float s = 1.f / (1.f + expf(-slog[e]));
            sc[e]  = s;
            scc[e] = s + bias[e];
        }
        int ids[TOPK]; float wts[TOPK]; float sum = 0.f;
        bool used[NE];
        #pragma unroll
        for (int e = 0; e < NE; e++) used[e] = false;
        #pragma unroll
        for (int k = 0; k < TOPK; k++) {
            int bi = 0; float bv = -1e30f;
            for (int e = 0; e < NE; e++)
                if (!used[e] && scc[e] > bv) { bv = scc[e]; bi = e; }  // strict > : lowest idx on tie
            used[bi] = true; ids[k] = bi; wts[k] = sc[bi]; sum += sc[bi];
        }
        float inv = ROUTED_SCALE / sum;
        float zw = 0.f;
        int nk = 0;
        #pragma unroll
        for (int k = 0; k < TOPK; k++) {
            float w = wts[k] * inv;
            if (ids[k] >= E_EXP) {
                zw += w;
            } else {
                int e = ids[k];
                int pos = atomicAdd(&g_count[e], 1);
                g_tok[e * CAP + pos] = t;
                g_slots[t * TOPK + nk] = e * CAP + pos;
                g_wts[t * TOPK + nk] = w;
                nk++;
            }
        }
        g_nk[t] = nk;
        g_zero_w[t] = zw;
    }
}

// ---------------- mma + cp.async helpers ----------------
__device__ __forceinline__ uint32_t f2tf(uint32_t bits) {
    uint32_t r;
    asm("cvt.rna.tf32.f32 %0, %1;" : "=r"(r) : "r"(bits));
    return r;
}
__device__ __forceinline__ void mma_tf32(float* d, const uint32_t* a, const uint32_t* b) {
    asm volatile(
        "mma.sync.aligned.m16n8k8.row.col.f32.tf32.tf32.f32 "
        "{%0,%1,%2,%3}, {%4,%5,%6,%7}, {%8,%9}, {%0,%1,%2,%3};\n"
        : "+f"(d[0]), "+f"(d[1]), "+f"(d[2]), "+f"(d[3])
        : "r"(a[0]), "r"(a[1]), "r"(a[2]), "r"(a[3]),
          "r"(b[0]), "r"(b[1]));
}
__device__ __forceinline__ uint32_t smem_u32(const void* p) {
    uint32_t a;
    asm("{ .reg .u64 t; cvta.to.shared.u64 t, %1; cvt.u32.u64 %0, t; }"
        : "=r"(a) : "l"(p));
    return a;
}
__device__ __forceinline__ void cp16(uint32_t d, const void* s) {
    asm volatile("cp.async.cg.shared.global [%0], [%1], 16;" :: "r"(d), "l"(s));
}
__device__ __forceinline__ void cp_commit() { asm volatile("cp.async.commit_group;" ::: "memory"); }
__device__ __forceinline__ void cp_wait1()  { asm volatile("cp.async.wait_group 1;" ::: "memory"); }

// ---------------- GEMM tiling ----------------
#define BM 128
#define BN 128
#define BK 16
#define SPAD 20                    // (20g+tg)%32 distinct -> conflict-free frag reads + cp stores
#define ABUF (BM * SPAD)           // words
#define BBUF (BN * SPAD)
#define STW  (ABUF + BBUF)         // words per stage = 5120
#define STAGES 3
#define SMEM_BYTES (STAGES * STW * 4)   // 61440 B

// Core pipelined tile compute: 4 warps, 64x64 warp tiles.
// Fragments are RNA-rounded to tf32 AFTER the shared load (restores R3 numerics
// while keeping raw-fp32 cp.async staging).
template<int NKT>
__device__ __forceinline__ void gemm_tile(uint32_t sb,
                                          const float* aptr,
                                          const float* bptr,
                                          float acc[4][8][4],
                                          int wm, int wn, int g, int tg,
                                          int tid) {
    uint32_t adst = sb + (uint32_t)(tid * SPAD) * 4;
    uint32_t bdst = sb + (uint32_t)(ABUF + tid * SPAD) * 4;

    // prologue: stages 0,1
    #pragma unroll
    for (int s = 0; s < 2; s++) {
        uint32_t st = (uint32_t)(s * STW) * 4;
        #pragma unroll
        for (int j = 0; j < 4; j++) {
            cp16(adst + st + j * 16, aptr + s * BK + j * 4);
            cp16(bdst + st + j * 16, bptr + s * BK + j * 4);
        }
        cp_commit();
    }

    #pragma unroll 1
    for (int c = 0; c < NKT; c++) {
        int st = c % STAGES;
        cp_wait1();            // stage c's group complete (<=1 pending)
        __syncthreads();

        // issue loads for chunk c+2 into stage (c+2)%STAGES (the consumed one)
        if (c + 2 < NKT) {
            int s2 = (c + 2) % STAGES;
            uint32_t stoff = (uint32_t)(s2 * STW) * 4;
            int k0 = (c + 2) * BK;
            #pragma unroll
            for (int j = 0; j < 4; j++) {
                cp16(adst + stoff + j * 16, aptr + k0 + j * 4);
                cp16(bdst + stoff + j * 16, bptr + k0 + j * 4);
            }
        }
        cp_commit();           // keep group accounting uniform

        {
            uint32_t abase = sb + (uint32_t)(st * STW) * 4;
            uint32_t bbase = abase + (uint32_t)ABUF * 4;
            #pragma unroll
            for (int k8 = 0; k8 < BK; k8 += 8) {
                uint32_t afr[4][4], bfr[8][2];
                #pragma unroll
                for (int mt = 0; mt < 4; mt++) {
                    int r0 = wm * 64 + mt * 16;
                    uint32_t p0 = abase + ((r0 + g) * SPAD + k8 + tg) * 4;
                    uint32_t p1 = abase + ((r0 + g + 8) * SPAD + k8 + tg) * 4;
                    asm volatile("ld.shared.b32 %0, [%1];" : "=r"(afr[mt][0]) : "r"(p0));
                    asm volatile("ld.shared.b32 %0, [%1];" : "=r"(afr[mt][1]) : "r"(p1));
                    asm volatile("ld.shared.b32 %0, [%1];" : "=r"(afr[mt][2]) : "r"(p0 + 16));
                    asm volatile("ld.shared.b32 %0, [%1];" : "=r"(afr[mt][3]) : "r"(p1 + 16));
                    afr[mt][0] = f2tf(afr[mt][0]);
                    afr[mt][1] = f2tf(afr[mt][1]);
                    afr[mt][2] = f2tf(afr[mt][2]);
                    afr[mt][3] = f2tf(afr[mt][3]);
                }
                #pragma unroll
                for (int nt = 0; nt < 8; nt++) {
                    int c0 = wn * 64 + nt * 8 + g;
                    uint32_t p = bbase + (c0 * SPAD + k8 + tg) * 4;
                    asm volatile("ld.shared.b32 %0, [%1];" : "=r"(bfr[nt][0]) : "r"(p));
                    asm volatile("ld.shared.b32 %0, [%1];" : "=r"(bfr[nt][1]) : "r"(p + 16));
                    bfr[nt][0] = f2tf(bfr[nt][0]);
                    bfr[nt][1] = f2tf(bfr[nt][1]);
                }
                #pragma unroll
                for (int mt = 0; mt < 4; mt++)
                    #pragma unroll
                    for (int nt = 0; nt < 8; nt++)
                        mma_tf32(acc[mt][nt], afr[mt], bfr[nt]);
            }
        }
        __syncthreads();
    }
}

// kernel 2: act = silu(x@w1^T)*(x@w3^T); B rows interleaved w1/w3 (64 features/block)
__global__ __launch_bounds__(128, 2)
void gemm1_kernel(const float* __restrict__ x,
                  const float* __restrict__ w1,
                  const float* __restrict__ w3) {
    int e   = blockIdx.z;
    int cnt = g_count[e];
    int m0  = blockIdx.y * BM;
    if (m0 >= cnt) return;
    int f0  = blockIdx.x * (BN / 2);

    extern __shared__ __align__(16) uint32_t smw[];
    uint32_t sb = smem_u32(smw);
    int tid = threadIdx.x, warp = tid >> 5, lane = tid & 31;
    int wm = warp >> 1, wn = warp & 1;
    int g = lane >> 2, tg = lane & 3;

    int arow = m0 + tid; if (arow >= cnt) arow = cnt - 1;
    int tok = g_tok[e * CAP + arow];
    const float* aptr = x + (size_t)tok * H_DIM;
    const float* bptr = ((tid & 1) ? w3 : w1)
                      + ((size_t)e * I_DIM + f0 + (tid >> 1)) * H_DIM;

    float acc[4][8][4];
    #pragma unroll
    for (int mt = 0; mt < 4; mt++)
        #pragma unroll
        for (int nt = 0; nt < 8; nt++)
            #pragma unroll
            for (int i = 0; i < 4; i++) acc[mt][nt][i] = 0.f;

    gemm_tile<H_DIM / BK>(sb, aptr, bptr, acc, wm, wn, g, tg, tid);

    // epilogue: col 2j=gate, 2j+1=up -> silu(gate)*up
    #pragma unroll
    for (int mt = 0; mt < 4; mt++) {
        int row = m0 + wm * 64 + mt * 16 + g;
        #pragma unroll
        for (int nt = 0; nt < 8; nt++) {
            int f = f0 + wn * 32 + nt * 4 + tg;
            float* d = acc[mt][nt];
            if (row < cnt) {
                float gt = d[0], up = d[1];
                g_act[((size_t)e * CAP + row) * I_DIM + f] = gt / (1.f + expf(-gt)) * up;
            }
            if (row + 8 < cnt) {
                float gt = d[2], up = d[3];
                g_act[((size_t)e * CAP + row + 8) * I_DIM + f] = gt / (1.f + expf(-gt)) * up;
            }
        }
    }
}

// kernel 3: y = act @ w2^T (per-slot output, deterministic)
__global__ __launch_bounds__(128, 2)
void gemm2_kernel(const float* __restrict__ w2) {
    int e   = blockIdx.z;
    int cnt = g_count[e];
    int m0  = blockIdx.y * BM;
    if (m0 >= cnt) return;
    int n0  = blockIdx.x * BN;

    extern __shared__ __align__(16) uint32_t smw[];
    uint32_t sb = smem_u32(smw);
    int tid = threadIdx.x, warp = tid >> 5, lane = tid & 31;
    int wm = warp >> 1, wn = warp & 1;
    int g = lane >> 2, tg = lane & 3;

    int arow = m0 + tid; if (arow >= cnt) arow = cnt - 1;
    const float* aptr = g_act + ((size_t)e * CAP + arow) * I_DIM;
    const float* bptr = w2 + ((size_t)e * H_DIM + n0 + tid) * I_DIM;

    float acc[4][8][4];
    #pragma unroll
    for (int mt = 0; mt < 4; mt++)
        #pragma unroll
        for (int nt = 0; nt < 8; nt++)
            #pragma unroll
            for (int i = 0; i < 4; i++) acc[mt][nt][i] = 0.f;

    gemm_tile<I_DIM / BK>(sb, aptr, bptr, acc, wm, wn, g, tg, tid);

    #pragma unroll
    for (int mt = 0; mt < 4; mt++) {
        int row = m0 + wm * 64 + mt * 16 + g;
        #pragma unroll
        for (int nt = 0; nt < 8; nt++) {
            int col = n0 + wn * 64 + nt * 8 + 2 * tg;
            float* d = acc[mt][nt];
            if (row < cnt)
                *(float2*)&g_y[((size_t)e * CAP + row) * H_DIM + col]
                    = make_float2(d[0], d[1]);
            if (row + 8 < cnt)
                *(float2*)&g_y[((size_t)e * CAP + row + 8) * H_DIM + col]
                    = make_float2(d[2], d[3]);
        }
    }
}

// ---------------- kernel 4: combine ----------------
__global__ __launch_bounds__(256)
void combine_kernel(const float* __restrict__ x, float* __restrict__ out) {
    int t = blockIdx.x;
    __shared__ int   s_n;
    __shared__ float s_zw;
    __shared__ int   s_slot[TOPK];
    __shared__ float s_w[TOPK];
    int tid = threadIdx.x;
    if (tid == 0) { s_n = g_nk[t]; s_zw = g_zero_w[t]; }
    if (tid < TOPK) { s_slot[tid] = g_slots[t * TOPK + tid]; s_w[tid] = g_wts[t * TOPK + tid]; }
    __syncthreads();
    int n = s_n; float zw = s_zw;

    const float* xrow = x + (size_t)t * H_DIM;
    float* orow = out + (size_t)t * H_DIM;
    for (int h = tid * 4; h < H_DIM; h += 256 * 4) {
        float4 xv = *(const float4*)(xrow + h);
        float4 o = make_float4(xv.x * zw, xv.y * zw, xv.z * zw, xv.w * zw);
        for (int k = 0; k < n; k++) {
            const float4 yv = *(const float4*)(g_y + (size_t)s_slot[k] * H_DIM + h);
            float wk = s_w[k];
            o.x += wk * yv.x; o.y += wk * yv.y; o.z += wk * yv.z; o.w += wk * yv.w;
        }
        *(float4*)(orow + h) = o;
    }
}

// ---------------- launcher ----------------
extern "C" void kernel_launch(void* const* d_in, const int* in_sizes, int n_in,
                              void* d_out, int out_size) {
    const float* x    = (const float*)d_in[0];
    const float* rw   = (const float*)d_in[1];
    const float* bias = (const float*)d_in[2];
    const float* w1   = (const float*)d_in[3];
    const float* w3   = (const float*)d_in[4];
    const float* w2   = (const float*)d_in[5];
    float* out = (float*)d_out;

    cudaFuncSetAttribute(gemm1_kernel, cudaFuncAttributeMaxDynamicSharedMemorySize, SMEM_BYTES);
    cudaFuncSetAttribute(gemm2_kernel, cudaFuncAttributeMaxDynamicSharedMemorySize, SMEM_BYTES);

    zero_counts_kernel<<<1, 32>>>();
    router_kernel<<<T_TOK, 256>>>(x, rw, bias);
    {
        dim3 g((2 * I_DIM) / BN, T_TOK / BM, E_EXP);  // 16 x 32 x 32
        gemm1_kernel<<<g, 128, SMEM_BYTES>>>(x, w1, w3);
    }
    {
        dim3 g(H_DIM / BN, T_TOK / BM, E_EXP);        // 16 x 32 x 32
        gemm2_kernel<<<g, 128, SMEM_BYTES>>>(w2);
    }
    combine_kernel<<<T_TOK, 256>>>(x, out);
}

// round 8
// speedup vs baseline: 1.3259x; 1.2469x over previous
#include <cuda_runtime.h>
#include <math.h>
#include <stdint.h>

// ---------------- problem constants ----------------
#define T_TOK 4096
#define H_DIM 2048
#define E_EXP 32
#define NE    48
#define I_DIM 1024
#define TOPK  6
#define ROUTED_SCALE 2.5f
#define CAP   4096

// ---------------- device scratch (static, no allocs) ----------------
__device__ int   g_count[E_EXP];
__device__ int   g_tok[E_EXP * CAP];
__device__ int   g_nk[T_TOK];
__device__ int   g_slots[T_TOK * TOPK];
__device__ float g_wts[T_TOK * TOPK];
__device__ float g_zero_w[T_TOK];
__device__ float g_act[(size_t)E_EXP * CAP * I_DIM];
__device__ float g_y[(size_t)E_EXP * CAP * H_DIM];

// ---------------- kernel 0 ----------------
__global__ void zero_counts_kernel() {
    int i = threadIdx.x;
    if (i < E_EXP) g_count[i] = 0;
}

// ---------------- kernel 1: router (exact fp32 — selection must not flip) ----------------
__global__ __launch_bounds__(256)
void router_kernel(const float* __restrict__ x,
                   const float* __restrict__ rw,
                   const float* __restrict__ bias) {
    int t   = blockIdx.x;
    int tid = threadIdx.x;
    __shared__ float sx[H_DIM];
    __shared__ float slog[NE];

    const float* xrow = x + (size_t)t * H_DIM;
    for (int i = tid; i < H_DIM; i += 256) sx[i] = xrow[i];
    __syncthreads();

    int warp = tid >> 5, lane = tid & 31;
    for (int e = warp; e < NE; e += 8) {
        const float* w = rw + (size_t)e * H_DIM;
        float acc = 0.f;
        for (int i = lane; i < H_DIM; i += 32) acc += sx[i] * w[i];
        #pragma unroll
        for (int o = 16; o; o >>= 1) acc += __shfl_xor_sync(0xffffffffu, acc, o);
        if (lane == 0) slog[e] = acc;
    }
    __syncthreads();

    if (tid == 0) {
        float sc[NE], scc[NE];
        #pragma unroll
        for (int e = 0; e < NE; e++) {
            float s = 1.f / (1.f + expf(-slog[e]));
            sc[e]  = s;
            scc[e] = s + bias[e];
        }
        int ids[TOPK]; float wts[TOPK]; float sum = 0.f;
        bool used[NE];
        #pragma unroll
        for (int e = 0; e < NE; e++) used[e] = false;
        #pragma unroll
        for (int k = 0; k < TOPK; k++) {
            int bi = 0; float bv = -1e30f;
            for (int e = 0; e < NE; e++)
                if (!used[e] && scc[e] > bv) { bv = scc[e]; bi = e; }  // strict > : lowest idx on tie
            used[bi] = true; ids[k] = bi; wts[k] = sc[bi]; sum += sc[bi];
        }
        float inv = ROUTED_SCALE / sum;
        float zw = 0.f;
        int nk = 0;
        #pragma unroll
        for (int k = 0; k < TOPK; k++) {
            float w = wts[k] * inv;
            if (ids[k] >= E_EXP) {
                zw += w;
            } else {
                int e = ids[k];
                int pos = atomicAdd(&g_count[e], 1);
                g_tok[e * CAP + pos] = t;
                g_slots[t * TOPK + nk] = e * CAP + pos;
                g_wts[t * TOPK + nk] = w;
                nk++;
            }
        }
        g_nk[t] = nk;
        g_zero_w[t] = zw;
    }
}

// ---------------- mma + cp.async helpers ----------------
__device__ __forceinline__ uint32_t f2tf(uint32_t bits) {
    uint32_t r;
    asm("cvt.rna.tf32.f32 %0, %1;" : "=r"(r) : "r"(bits));
    return r;
}
__device__ __forceinline__ void mma_tf32(float* d, const uint32_t* a, const uint32_t* b) {
    asm volatile(
        "mma.sync.aligned.m16n8k8.row.col.f32.tf32.tf32.f32 "
        "{%0,%1,%2,%3}, {%4,%5,%6,%7}, {%8,%9}, {%0,%1,%2,%3};\n"
        : "+f"(d[0]), "+f"(d[1]), "+f"(d[2]), "+f"(d[3])
        : "r"(a[0]), "r"(a[1]), "r"(a[2]), "r"(a[3]),
          "r"(b[0]), "r"(b[1]));
}
__device__ __forceinline__ uint32_t smem_u32(const void* p) {
    uint32_t a;
    asm("{ .reg .u64 t; cvta.to.shared.u64 t, %1; cvt.u32.u64 %0, t; }"
        : "=r"(a) : "l"(p));
    return a;
}
__device__ __forceinline__ void cp16(uint32_t d, const void* s) {
    asm volatile("cp.async.cg.shared.global [%0], [%1], 16;" :: "r"(d), "l"(s));
}
__device__ __forceinline__ void cp_commit() { asm volatile("cp.async.commit_group;" ::: "memory"); }
__device__ __forceinline__ void cp_wait1()  { asm volatile("cp.async.wait_group 1;" ::: "memory"); }

// ---------------- GEMM tiling ----------------
#define BM 128
#define BN 128
#define BK 16
#define SPAD 20                    // (20g+tg)%32 distinct -> conflict-free frag reads
#define ABUF (BM * SPAD)           // words
#define BBUF (BN * SPAD)
#define STW  (ABUF + BBUF)         // words per stage = 5120
#define STAGES 3
#define SMEM_BYTES (STAGES * STW * 4)   // 61440 B

// Core pipelined tile compute: 8 warps (2x4), 64x32 warp tiles, 256 threads.
// Thread t stages A row t>>1 half (t&1), B row t>>1 half (t&1): 4 cp16/chunk.
template<int NKT>
__device__ __forceinline__ void gemm_tile(uint32_t sb,
                                          const float* aptr,   // row base + half offset
                                          const float* bptr,   // row base + half offset
                                          float acc[4][4][4],
                                          int wm, int wn, int g, int tg,
                                          int tid) {
    uint32_t adst = sb + (uint32_t)((tid >> 1) * SPAD + (tid & 1) * 8) * 4;
    uint32_t bdst = sb + (uint32_t)(ABUF + (tid >> 1) * SPAD + (tid & 1) * 8) * 4;

    // prologue: stages 0,1
    #pragma unroll
    for (int s = 0; s < 2; s++) {
        uint32_t st = (uint32_t)(s * STW) * 4;
        #pragma unroll
        for (int j = 0; j < 2; j++) {
            cp16(adst + st + j * 16, aptr + s * BK + j * 4);
            cp16(bdst + st + j * 16, bptr + s * BK + j * 4);
        }
        cp_commit();
    }

    #pragma unroll 1
    for (int c = 0; c < NKT; c++) {
        int st = c % STAGES;
        cp_wait1();            // stage c's group complete (<=1 pending)
        __syncthreads();

        // issue loads for chunk c+2 into stage (c+2)%STAGES (the consumed one)
        if (c + 2 < NKT) {
            int s2 = (c + 2) % STAGES;
            uint32_t stoff = (uint32_t)(s2 * STW) * 4;
            int k0 = (c + 2) * BK;
            #pragma unroll
            for (int j = 0; j < 2; j++) {
                cp16(adst + stoff + j * 16, aptr + k0 + j * 4);
                cp16(bdst + stoff + j * 16, bptr + k0 + j * 4);
            }
        }
        cp_commit();           // keep group accounting uniform

        {
            uint32_t abase = sb + (uint32_t)(st * STW) * 4;
            uint32_t bbase = abase + (uint32_t)ABUF * 4;
            #pragma unroll
            for (int k8 = 0; k8 < BK; k8 += 8) {
                uint32_t afr[4][4], bfr[4][2];
                #pragma unroll
                for (int mt = 0; mt < 4; mt++) {
                    int r0 = wm * 64 + mt * 16;
                    uint32_t p0 = abase + ((r0 + g) * SPAD + k8 + tg) * 4;
                    uint32_t p1 = abase + ((r0 + g + 8) * SPAD + k8 + tg) * 4;
                    asm volatile("ld.shared.b32 %0, [%1];" : "=r"(afr[mt][0]) : "r"(p0));
                    asm volatile("ld.shared.b32 %0, [%1];" : "=r"(afr[mt][1]) : "r"(p1));
                    asm volatile("ld.shared.b32 %0, [%1];" : "=r"(afr[mt][2]) : "r"(p0 + 16));
                    asm volatile("ld.shared.b32 %0, [%1];" : "=r"(afr[mt][3]) : "r"(p1 + 16));
                    afr[mt][0] = f2tf(afr[mt][0]);
                    afr[mt][1] = f2tf(afr[mt][1]);
                    afr[mt][2] = f2tf(afr[mt][2]);
                    afr[mt][3] = f2tf(afr[mt][3]);
                }
                #pragma unroll
                for (int nt = 0; nt < 4; nt++) {
                    int c0 = wn * 32 + nt * 8 + g;
                    uint32_t p = bbase + (c0 * SPAD + k8 + tg) * 4;
                    asm volatile("ld.shared.b32 %0, [%1];" : "=r"(bfr[nt][0]) : "r"(p));
                    asm volatile("ld.shared.b32 %0, [%1];" : "=r"(bfr[nt][1]) : "r"(p + 16));
                    bfr[nt][0] = f2tf(bfr[nt][0]);
                    bfr[nt][1] = f2tf(bfr[nt][1]);
                }
                #pragma unroll
                for (int mt = 0; mt < 4; mt++)
                    #pragma unroll
                    for (int nt = 0; nt < 4; nt++)
                        mma_tf32(acc[mt][nt], afr[mt], bfr[nt]);
            }
        }
        __syncthreads();
    }
}

// kernel 2: act = silu(x@w1^T)*(x@w3^T); B rows interleaved w1/w3 (64 features/block)
__global__ __launch_bounds__(256, 2)
void gemm1_kernel(const float* __restrict__ x,
                  const float* __restrict__ w1,
                  const float* __restrict__ w3) {
    int e   = blockIdx.z;
    int cnt = g_count[e];
    int m0  = blockIdx.y * BM;
    if (m0 >= cnt) return;
    int f0  = blockIdx.x * (BN / 2);

    extern __shared__ __align__(16) uint32_t smw[];
    uint32_t sb = smem_u32(smw);
    int tid = threadIdx.x, warp = tid >> 5, lane = tid & 31;
    int wm = warp >> 2, wn = warp & 3;     // 2x4 warp grid, 64x32 warp tiles
    int g = lane >> 2, tg = lane & 3;

    int r = tid >> 1, half = (tid & 1) * 8;
    int arow = m0 + r; if (arow >= cnt) arow = cnt - 1;
    int tok = g_tok[e * CAP + arow];
    const float* aptr = x + (size_t)tok * H_DIM + half;
    const float* bptr = ((r & 1) ? w3 : w1)
                      + ((size_t)e * I_DIM + f0 + (r >> 1)) * H_DIM + half;

    float acc[4][4][4];
    #pragma unroll
    for (int mt = 0; mt < 4; mt++)
        #pragma unroll
        for (int nt = 0; nt < 4; nt++)
            #pragma unroll
            for (int i = 0; i < 4; i++) acc[mt][nt][i] = 0.f;

    gemm_tile<H_DIM / BK>(sb, aptr, bptr, acc, wm, wn, g, tg, tid);

    // epilogue: col 2j=gate, 2j+1=up -> silu(gate)*up
    #pragma unroll
    for (int mt = 0; mt < 4; mt++) {
        int row = m0 + wm * 64 + mt * 16 + g;
        #pragma unroll
        for (int nt = 0; nt < 4; nt++) {
            int f = f0 + wn * 16 + nt * 4 + tg;
            float* d = acc[mt][nt];
            if (row < cnt) {
                float gt = d[0], up = d[1];
                g_act[((size_t)e * CAP + row) * I_DIM + f] = gt / (1.f + expf(-gt)) * up;
            }
            if (row + 8 < cnt) {
                float gt = d[2], up = d[3];
                g_act[((size_t)e * CAP + row + 8) * I_DIM + f] = gt / (1.f + expf(-gt)) * up;
            }
        }
    }
}

// kernel 3: y = act @ w2^T (per-slot output, deterministic)
__global__ __launch_bounds__(256, 2)
void gemm2_kernel(const float* __restrict__ w2) {
    int e   = blockIdx.z;
    int cnt = g_count[e];
    int m0  = blockIdx.y * BM;
    if (m0 >= cnt) return;
    int n0  = blockIdx.x * BN;

    extern __shared__ __align__(16) uint32_t smw[];
    uint32_t sb = smem_u32(smw);
    int tid = threadIdx.x, warp = tid >> 5, lane = tid & 31;
    int wm = warp >> 2, wn = warp & 3;
    int g = lane >> 2, tg = lane & 3;

    int r = tid >> 1, half = (tid & 1) * 8;
    int arow = m0 + r; if (arow >= cnt) arow = cnt - 1;
    const float* aptr = g_act + ((size_t)e * CAP + arow) * I_DIM + half;
    const float* bptr = w2 + ((size_t)e * H_DIM + n0 + r) * I_DIM + half;

    float acc[4][4][4];
    #pragma unroll
    for (int mt = 0; mt < 4; mt++)
        #pragma unroll
        for (int nt = 0; nt < 4; nt++)
            #pragma unroll
            for (int i = 0; i < 4; i++) acc[mt][nt][i] = 0.f;

    gemm_tile<I_DIM / BK>(sb, aptr, bptr, acc, wm, wn, g, tg, tid);

    #pragma unroll
    for (int mt = 0; mt < 4; mt++) {
        int row = m0 + wm * 64 + mt * 16 + g;
        #pragma unroll
        for (int nt = 0; nt < 4; nt++) {
            int col = n0 + wn * 32 + nt * 8 + 2 * tg;
            float* d = acc[mt][nt];
            if (row < cnt)
                *(float2*)&g_y[((size_t)e * CAP + row) * H_DIM + col]
                    = make_float2(d[0], d[1]);
            if (row + 8 < cnt)
                *(float2*)&g_y[((size_t)e * CAP + row + 8) * H_DIM + col]
                    = make_float2(d[2], d[3]);
        }
    }
}

// ---------------- kernel 4: combine ----------------
__global__ __launch_bounds__(256)
void combine_kernel(const float* __restrict__ x, float* __restrict__ out) {
    int t = blockIdx.x;
    __shared__ int   s_n;
    __shared__ float s_zw;
    __shared__ int   s_slot[TOPK];
    __shared__ float s_w[TOPK];
    int tid = threadIdx.x;
    if (tid == 0) { s_n = g_nk[t]; s_zw = g_zero_w[t]; }
    if (tid < TOPK) { s_slot[tid] = g_slots[t * TOPK + tid]; s_w[tid] = g_wts[t * TOPK + tid]; }
    __syncthreads();
    int n = s_n; float zw = s_zw;

    const float* xrow = x + (size_t)t * H_DIM;
    float* orow = out + (size_t)t * H_DIM;
    for (int h = tid * 4; h < H_DIM; h += 256 * 4) {
        float4 xv = *(const float4*)(xrow + h);
        float4 o = make_float4(xv.x * zw, xv.y * zw, xv.z * zw, xv.w * zw);
        for (int k = 0; k < n; k++) {
            const float4 yv = *(const float4*)(g_y + (size_t)s_slot[k] * H_DIM + h);
            float wk = s_w[k];
            o.x += wk * yv.x; o.y += wk * yv.y; o.z += wk * yv.z; o.w += wk * yv.w;
        }
        *(float4*)(orow + h) = o;
    }
}

// ---------------- launcher ----------------
extern "C" void kernel_launch(void* const* d_in, const int* in_sizes, int n_in,
                              void* d_out, int out_size) {
    const float* x    = (const float*)d_in[0];
    const float* rw   = (const float*)d_in[1];
    const float* bias = (const float*)d_in[2];
    const float* w1   = (const float*)d_in[3];
    const float* w3   = (const float*)d_in[4];
    const float* w2   = (const float*)d_in[5];
    float* out = (float*)d_out;

    cudaFuncSetAttribute(gemm1_kernel, cudaFuncAttributeMaxDynamicSharedMemorySize, SMEM_BYTES);
    cudaFuncSetAttribute(gemm2_kernel, cudaFuncAttributeMaxDynamicSharedMemorySize, SMEM_BYTES);

    zero_counts_kernel<<<1, 32>>>();
    router_kernel<<<T_TOK, 256>>>(x, rw, bias);
    {
        dim3 g((2 * I_DIM) / BN, T_TOK / BM, E_EXP);  // 16 x 32 x 32
        gemm1_kernel<<<g, 256, SMEM_BYTES>>>(x, w1, w3);
    }
    {
        dim3 g(H_DIM / BN, T_TOK / BM, E_EXP);        // 16 x 32 x 32
        gemm2_kernel<<<g, 256, SMEM_BYTES>>>(w2);
    }
    combine_kernel<<<T_TOK, 256>>>(x, out);
}

// round 9
// speedup vs baseline: 1.3796x; 1.0405x over previous
#include <cuda_runtime.h>
#include <math.h>
#include <stdint.h>

// ---------------- problem constants ----------------
#define T_TOK 4096
#define H_DIM 2048
#define E_EXP 32
#define NE    48
#define I_DIM 1024
#define TOPK  6
#define ROUTED_SCALE 2.5f
#define CAP   4096

// ---------------- device scratch (static, no allocs) ----------------
__device__ int   g_count[E_EXP];
__device__ int   g_tok[E_EXP * CAP];
__device__ int   g_nk[T_TOK];
__device__ int   g_slots[T_TOK * TOPK];
__device__ float g_wts[T_TOK * TOPK];
__device__ float g_zero_w[T_TOK];
__device__ float g_xtf[(size_t)T_TOK * H_DIM];          // x pre-rounded to tf32
__device__ float g_act[(size_t)E_EXP * CAP * I_DIM];    // stored tf32-rounded
__device__ float g_y[(size_t)E_EXP * CAP * H_DIM];

// ---------------- kernel 0 ----------------
__global__ void zero_counts_kernel() {
    int i = threadIdx.x;
    if (i < E_EXP) g_count[i] = 0;
}

// ---------------- helpers ----------------
__device__ __forceinline__ uint32_t f2tf_bits(uint32_t bits) {
    uint32_t r;
    asm("cvt.rna.tf32.f32 %0, %1;" : "=r"(r) : "r"(bits));
    return r;
}
__device__ __forceinline__ float f2tf_f(float f) {
    uint32_t r;
    asm("cvt.rna.tf32.f32 %0, %1;" : "=r"(r) : "f"(f));
    return __uint_as_float(r);
}

// ---------------- kernel 0b: pre-round x to tf32 ----------------
__global__ __launch_bounds__(256)
void round_x_kernel(const float* __restrict__ x) {
    size_t i = ((size_t)blockIdx.x * 256 + threadIdx.x) * 4;
    if (i < (size_t)T_TOK * H_DIM) {
        float4 v = *(const float4*)(x + i);
        v.x = f2tf_f(v.x); v.y = f2tf_f(v.y); v.z = f2tf_f(v.z); v.w = f2tf_f(v.w);
        *(float4*)(g_xtf + i) = v;
    }
}

// ---------------- kernel 1: router (exact fp32 — selection must not flip) ----------------
__global__ __launch_bounds__(256)
void router_kernel(const float* __restrict__ x,
                   const float* __restrict__ rw,
                   const float* __restrict__ bias) {
    int t   = blockIdx.x;
    int tid = threadIdx.x;
    __shared__ float sx[H_DIM];
    __shared__ float slog[NE];

    const float* xrow = x + (size_t)t * H_DIM;
    for (int i = tid; i < H_DIM; i += 256) sx[i] = xrow[i];
    __syncthreads();

    int warp = tid >> 5, lane = tid & 31;
    for (int e = warp; e < NE; e += 8) {
        const float* w = rw + (size_t)e * H_DIM;
        float acc = 0.f;
        for (int i = lane; i < H_DIM; i += 32) acc += sx[i] * w[i];
        #pragma unroll
        for (int o = 16; o; o >>= 1) acc += __shfl_xor_sync(0xffffffffu, acc, o);
        if (lane == 0) slog[e] = acc;
    }
    __syncthreads();

    if (tid == 0) {
        float sc[NE], scc[NE];
        #pragma unroll
        for (int e = 0; e < NE; e++) {
            float s = 1.f / (1.f + expf(-slog[e]));
            sc[e]  = s;
            scc[e] = s + bias[e];
        }
        int ids[TOPK]; float wts[TOPK]; float sum = 0.f;
        bool used[NE];
        #pragma unroll
        for (int e = 0; e < NE; e++) used[e] = false;
        #pragma unroll
        for (int k = 0; k < TOPK; k++) {
            int bi = 0; float bv = -1e30f;
            for (int e = 0; e < NE; e++)
                if (!used[e] && scc[e] > bv) { bv = scc[e]; bi = e; }  // strict > : lowest idx on tie
            used[bi] = true; ids[k] = bi; wts[k] = sc[bi]; sum += sc[bi];
        }
        float inv = ROUTED_SCALE / sum;
        float zw = 0.f;
        int nk = 0;
        #pragma unroll
        for (int k = 0; k < TOPK; k++) {
            float w = wts[k] * inv;
            if (ids[k] >= E_EXP) {
                zw += w;
            } else {
                int e = ids[k];
                int pos = atomicAdd(&g_count[e], 1);
                g_tok[e * CAP + pos] = t;
                g_slots[t * TOPK + nk] = e * CAP + pos;
                g_wts[t * TOPK + nk] = w;
                nk++;
            }
        }
        g_nk[t] = nk;
        g_zero_w[t] = zw;
    }
}

// ---------------- mma + cp.async helpers ----------------
__device__ __forceinline__ void mma_tf32(float* d, const uint32_t* a, const uint32_t* b) {
    asm volatile(
        "mma.sync.aligned.m16n8k8.row.col.f32.tf32.tf32.f32 "
        "{%0,%1,%2,%3}, {%4,%5,%6,%7}, {%8,%9}, {%0,%1,%2,%3};\n"
        : "+f"(d[0]), "+f"(d[1]), "+f"(d[2]), "+f"(d[3])
        : "r"(a[0]), "r"(a[1]), "r"(a[2]), "r"(a[3]),
          "r"(b[0]), "r"(b[1]));
}
__device__ __forceinline__ uint32_t smem_u32(const void* p) {
    uint32_t a;
    asm("{ .reg .u64 t; cvta.to.shared.u64 t, %1; cvt.u32.u64 %0, t; }"
        : "=r"(a) : "l"(p));
    return a;
}
__device__ __forceinline__ void cp16(uint32_t d, const void* s) {
    asm volatile("cp.async.cg.shared.global [%0], [%1], 16;" :: "r"(d), "l"(s));
}
__device__ __forceinline__ void cp_commit() { asm volatile("cp.async.commit_group;" ::: "memory"); }
__device__ __forceinline__ void cp_wait1()  { asm volatile("cp.async.wait_group 1;" ::: "memory"); }

// ---------------- GEMM tiling ----------------
#define BM 128
#define BN 128
#define BK 16
#define SPAD 20                    // (20g+tg)%32 distinct -> conflict-free frag reads
#define ABUF (BM * SPAD)           // words
#define BBUF (BN * SPAD)
#define STW  (ABUF + BBUF)         // words per stage = 5120
#define STAGES 3
#define SMEM_BYTES (STAGES * STW * 4)   // 61440 B

// Core pipelined tile compute: 8 warps (2x4), 64x32 warp tiles, 256 threads.
// A source is PRE-ROUNDED tf32 (no cvt); B (weights) cvt'd at the fragment.
// One __syncthreads per chunk: the top barrier of iter c+1 orders compute(c)
// before the cp.async (issued after it) that overwrites stage c%3.
template<int NKT>
__device__ __forceinline__ void gemm_tile(uint32_t sb,
                                          const float* aptr,   // row base + half offset
                                          const float* bptr,   // row base + half offset
                                          float acc[4][4][4],
                                          int wm, int wn, int g, int tg,
                                          int tid) {
    uint32_t adst = sb + (uint32_t)((tid >> 1) * SPAD + (tid & 1) * 8) * 4;
    uint32_t bdst = sb + (uint32_t)(ABUF + (tid >> 1) * SPAD + (tid & 1) * 8) * 4;

    // prologue: stages 0,1
    #pragma unroll
    for (int s = 0; s < 2; s++) {
        uint32_t st = (uint32_t)(s * STW) * 4;
        #pragma unroll
        for (int j = 0; j < 2; j++) {
            cp16(adst + st + j * 16, aptr + s * BK + j * 4);
            cp16(bdst + st + j * 16, bptr + s * BK + j * 4);
        }
        cp_commit();
    }

    #pragma unroll 1
    for (int c = 0; c < NKT; c++) {
        int st = c % STAGES;
        cp_wait1();            // chunk c's group complete (<=1 pending)
        __syncthreads();       // also orders compute(c-1) before overwrite below

        // issue loads for chunk c+2 into stage (c+2)%STAGES (consumed at c-1)
        if (c + 2 < NKT) {
            int s2 = (c + 2) % STAGES;
            uint32_t stoff = (uint32_t)(s2 * STW) * 4;
            int k0 = (c + 2) * BK;
            #pragma unroll
            for (int j = 0; j < 2; j++) {
                cp16(adst + stoff + j * 16, aptr + k0 + j * 4);
                cp16(bdst + stoff + j * 16, bptr + k0 + j * 4);
            }
        }
        cp_commit();           // keep group accounting uniform

        {
            uint32_t abase = sb + (uint32_t)(st * STW) * 4;
            uint32_t bbase = abase + (uint32_t)ABUF * 4;
            #pragma unroll
            for (int k8 = 0; k8 < BK; k8 += 8) {
                uint32_t afr[4][4], bfr[4][2];
                #pragma unroll
                for (int mt = 0; mt < 4; mt++) {
                    int r0 = wm * 64 + mt * 16;
                    uint32_t p0 = abase + ((r0 + g) * SPAD + k8 + tg) * 4;
                    uint32_t p1 = abase + ((r0 + g + 8) * SPAD + k8 + tg) * 4;
                    asm volatile("ld.shared.b32 %0, [%1];" : "=r"(afr[mt][0]) : "r"(p0));
                    asm volatile("ld.shared.b32 %0, [%1];" : "=r"(afr[mt][1]) : "r"(p1));
                    asm volatile("ld.shared.b32 %0, [%1];" : "=r"(afr[mt][2]) : "r"(p0 + 16));
                    asm volatile("ld.shared.b32 %0, [%1];" : "=r"(afr[mt][3]) : "r"(p1 + 16));
                }
                #pragma unroll
                for (int nt = 0; nt < 4; nt++) {
                    int c0 = wn * 32 + nt * 8 + g;
                    uint32_t p = bbase + (c0 * SPAD + k8 + tg) * 4;
                    asm volatile("ld.shared.b32 %0, [%1];" : "=r"(bfr[nt][0]) : "r"(p));
                    asm volatile("ld.shared.b32 %0, [%1];" : "=r"(bfr[nt][1]) : "r"(p + 16));
                    bfr[nt][0] = f2tf_bits(bfr[nt][0]);
                    bfr[nt][1] = f2tf_bits(bfr[nt][1]);
                }
                #pragma unroll
                for (int mt = 0; mt < 4; mt++)
                    #pragma unroll
                    for (int nt = 0; nt < 4; nt++)
                        mma_tf32(acc[mt][nt], afr[mt], bfr[nt]);
            }
        }
    }
    __syncthreads();   // protect smem before epilogue-era reuse / kernel end
}

// kernel 2: act = silu(x@w1^T)*(x@w3^T); B rows interleaved w1/w3 (64 features/block)
__global__ __launch_bounds__(256, 2)
void gemm1_kernel(const float* __restrict__ w1,
                  const float* __restrict__ w3) {
    int e   = blockIdx.z;
    int cnt = g_count[e];
    int m0  = blockIdx.y * BM;
    if (m0 >= cnt) return;
    int f0  = blockIdx.x * (BN / 2);

    extern __shared__ __align__(16) uint32_t smw[];
    uint32_t sb = smem_u32(smw);
    int tid = threadIdx.x, warp = tid >> 5, lane = tid & 31;
    int wm = warp >> 2, wn = warp & 3;     // 2x4 warp grid, 64x32 warp tiles
    int g = lane >> 2, tg = lane & 3;

    int r = tid >> 1, half = (tid & 1) * 8;
    int arow = m0 + r; if (arow >= cnt) arow = cnt - 1;
    int tok = g_tok[e * CAP + arow];
    const float* aptr = g_xtf + (size_t)tok * H_DIM + half;
    const float* bptr = ((r & 1) ? w3 : w1)
                      + ((size_t)e * I_DIM + f0 + (r >> 1)) * H_DIM + half;

    float acc[4][4][4];
    #pragma unroll
    for (int mt = 0; mt < 4; mt++)
        #pragma unroll
        for (int nt = 0; nt < 4; nt++)
            #pragma unroll
            for (int i = 0; i < 4; i++) acc[mt][nt][i] = 0.f;

    gemm_tile<H_DIM / BK>(sb, aptr, bptr, acc, wm, wn, g, tg, tid);

    // epilogue: col 2j=gate, 2j+1=up -> silu(gate)*up, stored tf32-rounded
    #pragma unroll
    for (int mt = 0; mt < 4; mt++) {
        int row = m0 + wm * 64 + mt * 16 + g;
        #pragma unroll
        for (int nt = 0; nt < 4; nt++) {
            int f = f0 + wn * 16 + nt * 4 + tg;
            float* d = acc[mt][nt];
            if (row < cnt) {
                float gt = d[0], up = d[1];
                g_act[((size_t)e * CAP + row) * I_DIM + f] =
                    f2tf_f(gt / (1.f + expf(-gt)) * up);
            }
            if (row + 8 < cnt) {
                float gt = d[2], up = d[3];
                g_act[((size_t)e * CAP + row + 8) * I_DIM + f] =
                    f2tf_f(gt / (1.f + expf(-gt)) * up);
            }
        }
    }
}

// kernel 3: y = act @ w2^T (per-slot output, deterministic)
__global__ __launch_bounds__(256, 2)
void gemm2_kernel(const float* __restrict__ w2) {
    int e   = blockIdx.z;
    int cnt = g_count[e];
    int m0  = blockIdx.y * BM;
    if (m0 >= cnt) return;
    int n0  = blockIdx.x * BN;

    extern __shared__ __align__(16) uint32_t smw[];
    uint32_t sb = smem_u32(smw);
    int tid = threadIdx.x, warp = tid >> 5, lane = tid & 31;
    int wm = warp >> 2, wn = warp & 3;
    int g = lane >> 2, tg = lane & 3;

    int r = tid >> 1, half = (tid & 1) * 8;
    int arow = m0 + r; if (arow >= cnt) arow = cnt - 1;
    const float* aptr = g_act + ((size_t)e * CAP + arow) * I_DIM + half;
    const float* bptr = w2 + ((size_t)e * H_DIM + n0 + r) * I_DIM + half;

    float acc[4][4][4];
    #pragma unroll
    for (int mt = 0; mt < 4; mt++)
        #pragma unroll
        for (int nt = 0; nt < 4; nt++)
            #pragma unroll
            for (int i = 0; i < 4; i++) acc[mt][nt][i] = 0.f;

    gemm_tile<I_DIM / BK>(sb, aptr, bptr, acc, wm, wn, g, tg, tid);

    #pragma unroll
    for (int mt = 0; mt < 4; mt++) {
        int row = m0 + wm * 64 + mt * 16 + g;
        #pragma unroll
        for (int nt = 0; nt < 4; nt++) {
            int col = n0 + wn * 32 + nt * 8 + 2 * tg;
            float* d = acc[mt][nt];
            if (row < cnt)
                *(float2*)&g_y[((size_t)e * CAP + row) * H_DIM + col]
                    = make_float2(d[0], d[1]);
            if (row + 8 < cnt)
                *(float2*)&g_y[((size_t)e * CAP + row + 8) * H_DIM + col]
                    = make_float2(d[2], d[3]);
        }
    }
}

// ---------------- kernel 4: combine ----------------
__global__ __launch_bounds__(256)
void combine_kernel(const float* __restrict__ x, float* __restrict__ out) {
    int t = blockIdx.x;
    __shared__ int   s_n;
    __shared__ float s_zw;
    __shared__ int   s_slot[TOPK];
    __shared__ float s_w[TOPK];
    int tid = threadIdx.x;
    if (tid == 0) { s_n = g_nk[t]; s_zw = g_zero_w[t]; }
    if (tid < TOPK) { s_slot[tid] = g_slots[t * TOPK + tid]; s_w[tid] = g_wts[t * TOPK + tid]; }
    __syncthreads();
    int n = s_n; float zw = s_zw;

    const float* xrow = x + (size_t)t * H_DIM;
    float* orow = out + (size_t)t * H_DIM;
    for (int h = tid * 4; h < H_DIM; h += 256 * 4) {
        float4 xv = *(const float4*)(xrow + h);
        float4 o = make_float4(xv.x * zw, xv.y * zw, xv.z * zw, xv.w * zw);
        for (int k = 0; k < n; k++) {
            const float4 yv = *(const float4*)(g_y + (size_t)s_slot[k] * H_DIM + h);
            float wk = s_w[k];
            o.x += wk * yv.x; o.y += wk * yv.y; o.z += wk * yv.z; o.w += wk * yv.w;
        }
        *(float4*)(orow + h) = o;
    }
}

// ---------------- launcher ----------------
extern "C" void kernel_launch(void* const* d_in, const int* in_sizes, int n_in,
                              void* d_out, int out_size) {
    const float* x    = (const float*)d_in[0];
    const float* rw   = (const float*)d_in[1];
    const float* bias = (const float*)d_in[2];
    const float* w1   = (const float*)d_in[3];
    const float* w3   = (const float*)d_in[4];
    const float* w2   = (const float*)d_in[5];
    float* out = (float*)d_out;

    cudaFuncSetAttribute(gemm1_kernel, cudaFuncAttributeMaxDynamicSharedMemorySize, SMEM_BYTES);
    cudaFuncSetAttribute(gemm2_kernel, cudaFuncAttributeMaxDynamicSharedMemorySize, SMEM_BYTES);

    zero_counts_kernel<<<1, 32>>>();
    round_x_kernel<<<(T_TOK * H_DIM / 4 + 255) / 256, 256>>>(x);
    router_kernel<<<T_TOK, 256>>>(x, rw, bias);
    {
        dim3 g((2 * I_DIM) / BN, T_TOK / BM, E_EXP);  // 16 x 32 x 32
        gemm1_kernel<<<g, 256, SMEM_BYTES>>>(w1, w3);
    }
    {
        dim3 g(H_DIM / BN, T_TOK / BM, E_EXP);        // 16 x 32 x 32
        gemm2_kernel<<<g, 256, SMEM_BYTES>>>(w2);
    }
    combine_kernel<<<T_TOK, 256>>>(x, out);
}